// round 2
// baseline (speedup 1.0000x reference)
#include <cuda_runtime.h>
#include <cuda_bf16.h>
#include <cstdint>

// Problem constants
#define Bb 2
#define Ss 2048
#define Dd 1024
#define Hh 16
#define Kk 64
#define BH (Bb*Hh)          // 32
#define SCALE 0.125f        // 1/sqrt(64)

// ---------------- scratch (static device globals; no allocation) -------------
__device__ float g_Q[(size_t)BH * Ss * Kk];       // [b,h,s,k] 16 MB
__device__ float g_K[(size_t)BH * Ss * Kk];       // 16 MB
__device__ float g_V[(size_t)BH * Ss * Kk];       // 16 MB
__device__ float g_heads[(size_t)Bb * Ss * Hh * Kk]; // [b,s,h*K] 16 MB

// =============================================================================
// Kernel 1: QKV projection.  For each (b,h,which): X[b] (S x D) @ W[h] (D x 64) + bias
// BM=64, BN=64 (full), BK=32, 256 threads, 4x4 micro-tile.
// grid: (S/64, B*H, 3)
// =============================================================================
__global__ __launch_bounds__(256) void qkv_kernel(
    const float* __restrict__ x,
    const float* __restrict__ W_Q, const float* __restrict__ b_Q,
    const float* __restrict__ W_K, const float* __restrict__ b_K,
    const float* __restrict__ W_V, const float* __restrict__ b_V)
{
    const int stile = blockIdx.x;     // s-tile
    const int bh    = blockIdx.y;     // 0..31
    const int which = blockIdx.z;     // 0=Q 1=K 2=V
    const int b = bh / Hh, h = bh % Hh;

    const float* W    = (which == 0) ? W_Q : (which == 1) ? W_K : W_V;
    const float* bias = (which == 0) ? b_Q : (which == 1) ? b_K : b_V;
    float*       out  = (which == 0) ? g_Q : (which == 1) ? g_K : g_V;

    __shared__ float As[32][65];   // As[dd][r] = x[s0+r][d0+dd]
    __shared__ float Bs[32][64];   // Bs[dd][c] = W[d0+dd][c]

    const int tid = threadIdx.x;
    const int s0 = stile * 64;
    const float* Ax = x + ((size_t)b * Ss + s0) * Dd;
    const float* Wh = W + (size_t)h * Dd * Kk;

    const int c0 = (tid % 16) * 4;
    const int r0 = (tid / 16) * 4;

    float4 acc[4];
    #pragma unroll
    for (int i = 0; i < 4; i++) acc[i] = make_float4(0.f, 0.f, 0.f, 0.f);

    for (int d0 = 0; d0 < Dd; d0 += 32) {
        // load A tile (64 rows x 32 d), coalesced along d
        {
            const int dd = tid % 32;
            const int rb = tid / 32;           // 0..7
            #pragma unroll
            for (int i = 0; i < 8; i++) {
                const int r = i * 8 + rb;
                As[dd][r] = Ax[(size_t)r * Dd + d0 + dd];
            }
        }
        // load B tile (32 d x 64 c), coalesced along c
        {
            const int c  = tid % 64;
            const int db = tid / 64;           // 0..3
            #pragma unroll
            for (int i = 0; i < 8; i++) {
                const int dd = i * 4 + db;
                Bs[dd][c] = Wh[(size_t)(d0 + dd) * Kk + c];
            }
        }
        __syncthreads();
        #pragma unroll
        for (int dd = 0; dd < 32; dd++) {
            const float4 bv = *(const float4*)&Bs[dd][c0];
            float a0 = As[dd][r0 + 0], a1 = As[dd][r0 + 1];
            float a2 = As[dd][r0 + 2], a3 = As[dd][r0 + 3];
            acc[0].x += a0 * bv.x; acc[0].y += a0 * bv.y; acc[0].z += a0 * bv.z; acc[0].w += a0 * bv.w;
            acc[1].x += a1 * bv.x; acc[1].y += a1 * bv.y; acc[1].z += a1 * bv.z; acc[1].w += a1 * bv.w;
            acc[2].x += a2 * bv.x; acc[2].y += a2 * bv.y; acc[2].z += a2 * bv.z; acc[2].w += a2 * bv.w;
            acc[3].x += a3 * bv.x; acc[3].y += a3 * bv.y; acc[3].z += a3 * bv.z; acc[3].w += a3 * bv.w;
        }
        __syncthreads();
    }

    const float4 bv = *(const float4*)&bias[h * Kk + c0];
    float* outp = out + ((size_t)bh * Ss + s0) * Kk;
    #pragma unroll
    for (int i = 0; i < 4; i++) {
        float4 v = acc[i];
        v.x += bv.x; v.y += bv.y; v.z += bv.z; v.w += bv.w;
        *(float4*)&outp[(size_t)(r0 + i) * Kk + c0] = v;
    }
}

// =============================================================================
// Kernel 2: attention for a 16-query slab of one (b,h).
//   scores (masked, scaled) -> smem, softmax in smem, write probs to d_out,
//   then P @ V fused.
// 256 threads, dynamic smem:
//   P  [16][2048] fp32, Qs [16][64], KV [128][68]
// grid: (S/16, B*H)
// =============================================================================
#define KV_STRIDE 68
#define SMEM_FLOATS (16*2048 + 16*64 + 128*KV_STRIDE)

__global__ __launch_bounds__(256) void attn_kernel(
    const int* __restrict__ mask, float* __restrict__ out_scores)
{
    extern __shared__ float sm[];
    float* P  = sm;                       // 16*2048
    float* Qs = sm + 16 * 2048;           // 16*64
    float* KV = Qs + 16 * 64;             // 128*68

    const int bh = blockIdx.y;
    const int b  = bh / Hh;
    const int s0 = blockIdx.x * 16;
    const int tid = threadIdx.x;

    const float* Qg = g_Q + ((size_t)bh * Ss + s0) * Kk;
    const float* Kg = g_K + (size_t)bh * Ss * Kk;
    const float* Vg = g_V + (size_t)bh * Ss * Kk;

    // load Q slab (16x64 = 1024 floats = 256 float4)
    ((float4*)Qs)[tid] = ((const float4*)Qg)[tid];

    // ---------------- scores: 16 x 2048 ----------------
    const int tc = tid % 32;        // key quad
    const int rc = tid / 32;        // 0..7 -> rows rc, rc+8
    const int* mrow0 = mask + ((size_t)b * Ss + s0 + rc)     * Ss;
    const int* mrow1 = mask + ((size_t)b * Ss + s0 + rc + 8) * Ss;

    for (int kt = 0; kt < Ss; kt += 128) {
        __syncthreads();   // protect KV reuse
        // load 128x64 K tile (rows padded to stride 68)
        for (int i = tid; i < 128 * 16; i += 256) {
            const int t = i / 16, kk = i % 16;
            ((float4*)(KV + t * KV_STRIDE))[kk] =
                ((const float4*)(Kg + (size_t)(kt + t) * Kk))[kk];
        }
        __syncthreads();

        float acc0[4] = {0.f, 0.f, 0.f, 0.f};
        float acc1[4] = {0.f, 0.f, 0.f, 0.f};
        #pragma unroll
        for (int k = 0; k < Kk; k += 4) {
            const float4 qa = *(const float4*)&Qs[rc * Kk + k];
            const float4 qb = *(const float4*)&Qs[(rc + 8) * Kk + k];
            #pragma unroll
            for (int i = 0; i < 4; i++) {
                const float4 kv = *(const float4*)&KV[(tc * 4 + i) * KV_STRIDE + k];
                acc0[i] += qa.x * kv.x + qa.y * kv.y + qa.z * kv.z + qa.w * kv.w;
                acc1[i] += qb.x * kv.x + qb.y * kv.y + qb.z * kv.z + qb.w * kv.w;
            }
        }
        #pragma unroll
        for (int i = 0; i < 4; i++) {
            const int t = kt + tc * 4 + i;
            P[rc * Ss + t]       = mrow0[t] ? acc0[i] * SCALE : -3.0e38f;
            P[(rc + 8) * Ss + t] = mrow1[t] ? acc1[i] * SCALE : -3.0e38f;
        }
    }
    __syncthreads();

    // ---------------- softmax (8 warps x 2 rows) + write probs --------------
    {
        const int warp = tid / 32, lane = tid % 32;
        #pragma unroll
        for (int rr = 0; rr < 2; rr++) {
            const int r = warp * 2 + rr;
            float* row = P + (size_t)r * Ss;
            float mx = -3.4e38f;
            for (int t = lane; t < Ss; t += 32) mx = fmaxf(mx, row[t]);
            #pragma unroll
            for (int o = 16; o > 0; o >>= 1) mx = fmaxf(mx, __shfl_xor_sync(0xffffffffu, mx, o));
            float sum = 0.f;
            for (int t = lane; t < Ss; t += 32) {
                const float e = __expf(row[t] - mx);
                row[t] = e;
                sum += e;
            }
            #pragma unroll
            for (int o = 16; o > 0; o >>= 1) sum += __shfl_xor_sync(0xffffffffu, sum, o);
            const float inv = 1.0f / sum;
            float* og = out_scores + ((size_t)bh * Ss + (s0 + r)) * Ss;
            for (int t = lane; t < Ss; t += 32) {
                const float p = row[t] * inv;
                row[t] = p;
                og[t]  = p;
            }
        }
    }
    __syncthreads();

    // ---------------- O = P @ V  (16 x 64) ----------------
    const int k0 = (tid % 16) * 4;
    const int r  = tid / 16;          // 0..15
    float4 o = make_float4(0.f, 0.f, 0.f, 0.f);
    for (int kt = 0; kt < Ss; kt += 128) {
        __syncthreads();
        for (int i = tid; i < 128 * 16; i += 256) {
            const int t = i / 16, kk = i % 16;
            ((float4*)(KV + t * KV_STRIDE))[kk] =
                ((const float4*)(Vg + (size_t)(kt + t) * Kk))[kk];
        }
        __syncthreads();
        #pragma unroll 4
        for (int t = 0; t < 128; t++) {
            const float p = P[(size_t)r * Ss + kt + t];
            const float4 v = *(const float4*)&KV[t * KV_STRIDE + k0];
            o.x += p * v.x; o.y += p * v.y; o.z += p * v.z; o.w += p * v.w;
        }
    }
    const int h = bh % Hh;
    *(float4*)&g_heads[((size_t)(b * Ss + s0 + r)) * (Hh * Kk) + h * Kk + k0] = o;
}

// =============================================================================
// Kernel 3: output projection.  heads [4096 x 1024] @ W_proj [1024 x 1024] + b_proj
// Same tiling as qkv. grid: (1024/64, 4096/64)
// =============================================================================
__global__ __launch_bounds__(256) void proj_kernel(
    const float* __restrict__ Wp, const float* __restrict__ bp,
    float* __restrict__ out)
{
    __shared__ float As[32][65];
    __shared__ float Bs[32][64];

    const int tid = threadIdx.x;
    const int n0 = blockIdx.x * 64;
    const int m0 = blockIdx.y * 64;
    const int HK = Hh * Kk;   // 1024

    const float* A = g_heads + (size_t)m0 * HK;

    const int c0 = (tid % 16) * 4;
    const int r0 = (tid / 16) * 4;

    float4 acc[4];
    #pragma unroll
    for (int i = 0; i < 4; i++) acc[i] = make_float4(0.f, 0.f, 0.f, 0.f);

    for (int d0 = 0; d0 < HK; d0 += 32) {
        {
            const int dd = tid % 32;
            const int rb = tid / 32;
            #pragma unroll
            for (int i = 0; i < 8; i++) {
                const int rr = i * 8 + rb;
                As[dd][rr] = A[(size_t)rr * HK + d0 + dd];
            }
        }
        {
            const int c  = tid % 64;
            const int db = tid / 64;
            #pragma unroll
            for (int i = 0; i < 8; i++) {
                const int dd = i * 4 + db;
                Bs[dd][c] = Wp[(size_t)(d0 + dd) * Dd + n0 + c];
            }
        }
        __syncthreads();
        #pragma unroll
        for (int dd = 0; dd < 32; dd++) {
            const float4 bv = *(const float4*)&Bs[dd][c0];
            float a0 = As[dd][r0 + 0], a1 = As[dd][r0 + 1];
            float a2 = As[dd][r0 + 2], a3 = As[dd][r0 + 3];
            acc[0].x += a0 * bv.x; acc[0].y += a0 * bv.y; acc[0].z += a0 * bv.z; acc[0].w += a0 * bv.w;
            acc[1].x += a1 * bv.x; acc[1].y += a1 * bv.y; acc[1].z += a1 * bv.z; acc[1].w += a1 * bv.w;
            acc[2].x += a2 * bv.x; acc[2].y += a2 * bv.y; acc[2].z += a2 * bv.z; acc[2].w += a2 * bv.w;
            acc[3].x += a3 * bv.x; acc[3].y += a3 * bv.y; acc[3].z += a3 * bv.z; acc[3].w += a3 * bv.w;
        }
        __syncthreads();
    }

    const float4 bv = *(const float4*)&bp[n0 + c0];
    #pragma unroll
    for (int i = 0; i < 4; i++) {
        float4 v = acc[i];
        v.x += bv.x; v.y += bv.y; v.z += bv.z; v.w += bv.w;
        *(float4*)&out[(size_t)(m0 + r0 + i) * Dd + n0 + c0] = v;
    }
}

// =============================================================================
extern "C" void kernel_launch(void* const* d_in, const int* in_sizes, int n_in,
                              void* d_out, int out_size)
{
    const float* x      = (const float*)d_in[0];
    const float* W_Q    = (const float*)d_in[1];
    const float* b_Q    = (const float*)d_in[2];
    const float* W_K    = (const float*)d_in[3];
    const float* b_K    = (const float*)d_in[4];
    const float* W_V    = (const float*)d_in[5];
    const float* b_V    = (const float*)d_in[6];
    const float* W_proj = (const float*)d_in[7];
    const float* b_proj = (const float*)d_in[8];
    const int*   amask  = (const int*)d_in[9];

    float* out        = (float*)d_out;                       // [B,S,D]
    float* out_scores = out + (size_t)Bb * Ss * Dd;          // [B,H,S,S]

    // QKV projections
    {
        dim3 grid(Ss / 64, BH, 3);
        qkv_kernel<<<grid, 256>>>(x, W_Q, b_Q, W_K, b_K, W_V, b_V);
    }

    // attention
    {
        const int smem = SMEM_FLOATS * (int)sizeof(float);   // ~170 KB
        cudaFuncSetAttribute(attn_kernel, cudaFuncAttributeMaxDynamicSharedMemorySize, smem);
        dim3 grid(Ss / 16, BH);
        attn_kernel<<<grid, 256, smem>>>(amask, out_scores);
    }

    // output projection
    {
        dim3 grid(Dd / 64, (Bb * Ss) / 64);
        proj_kernel<<<grid, 256>>>(W_proj, b_proj, out);
    }
}

// round 3
// speedup vs baseline: 1.0015x; 1.0015x over previous
#include <cuda_runtime.h>
#include <cuda_bf16.h>
#include <cstdint>

// Problem constants
#define Bb 2
#define Ss 2048
#define Dd 1024
#define Hh 16
#define Kk 64
#define BH (Bb*Hh)          // 32
#define SCALE 0.125f        // 1/sqrt(64)

// ---------------- scratch (static device globals; no allocation) -------------
__device__ float g_Q[(size_t)BH * Ss * Kk];       // [b,h,s,k] 16 MB
__device__ float g_K[(size_t)BH * Ss * Kk];       // 16 MB
__device__ float g_V[(size_t)BH * Ss * Kk];       // 16 MB
__device__ float g_heads[(size_t)Bb * Ss * Hh * Kk]; // [b,s,h*K] 16 MB

// =============================================================================
// Kernel 1: QKV projection.  For each (b,h,which): X[b] (S x D) @ W[h] (D x 64) + bias
// BM=64, BN=64 (full), BK=32, 256 threads, 4x4 micro-tile.
// grid: (S/64, B*H, 3)
// =============================================================================
__global__ __launch_bounds__(256) void qkv_kernel(
    const float* __restrict__ x,
    const float* __restrict__ W_Q, const float* __restrict__ b_Q,
    const float* __restrict__ W_K, const float* __restrict__ b_K,
    const float* __restrict__ W_V, const float* __restrict__ b_V)
{
    const int stile = blockIdx.x;     // s-tile
    const int bh    = blockIdx.y;     // 0..31
    const int which = blockIdx.z;     // 0=Q 1=K 2=V
    const int b = bh / Hh, h = bh % Hh;

    const float* W    = (which == 0) ? W_Q : (which == 1) ? W_K : W_V;
    const float* bias = (which == 0) ? b_Q : (which == 1) ? b_K : b_V;
    float*       out  = (which == 0) ? g_Q : (which == 1) ? g_K : g_V;

    __shared__ float As[32][65];   // As[dd][r] = x[s0+r][d0+dd]
    __shared__ float Bs[32][64];   // Bs[dd][c] = W[d0+dd][c]

    const int tid = threadIdx.x;
    const int s0 = stile * 64;
    const float* Ax = x + ((size_t)b * Ss + s0) * Dd;
    const float* Wh = W + (size_t)h * Dd * Kk;

    const int c0 = (tid % 16) * 4;
    const int r0 = (tid / 16) * 4;

    float4 acc[4];
    #pragma unroll
    for (int i = 0; i < 4; i++) acc[i] = make_float4(0.f, 0.f, 0.f, 0.f);

    for (int d0 = 0; d0 < Dd; d0 += 32) {
        // load A tile (64 rows x 32 d), coalesced along d
        {
            const int dd = tid % 32;
            const int rb = tid / 32;           // 0..7
            #pragma unroll
            for (int i = 0; i < 8; i++) {
                const int r = i * 8 + rb;
                As[dd][r] = Ax[(size_t)r * Dd + d0 + dd];
            }
        }
        // load B tile (32 d x 64 c), coalesced along c
        {
            const int c  = tid % 64;
            const int db = tid / 64;           // 0..3
            #pragma unroll
            for (int i = 0; i < 8; i++) {
                const int dd = i * 4 + db;
                Bs[dd][c] = Wh[(size_t)(d0 + dd) * Kk + c];
            }
        }
        __syncthreads();
        #pragma unroll
        for (int dd = 0; dd < 32; dd++) {
            const float4 bv = *(const float4*)&Bs[dd][c0];
            float a0 = As[dd][r0 + 0], a1 = As[dd][r0 + 1];
            float a2 = As[dd][r0 + 2], a3 = As[dd][r0 + 3];
            acc[0].x += a0 * bv.x; acc[0].y += a0 * bv.y; acc[0].z += a0 * bv.z; acc[0].w += a0 * bv.w;
            acc[1].x += a1 * bv.x; acc[1].y += a1 * bv.y; acc[1].z += a1 * bv.z; acc[1].w += a1 * bv.w;
            acc[2].x += a2 * bv.x; acc[2].y += a2 * bv.y; acc[2].z += a2 * bv.z; acc[2].w += a2 * bv.w;
            acc[3].x += a3 * bv.x; acc[3].y += a3 * bv.y; acc[3].z += a3 * bv.z; acc[3].w += a3 * bv.w;
        }
        __syncthreads();
    }

    const float4 bv = *(const float4*)&bias[h * Kk + c0];
    float* outp = out + ((size_t)bh * Ss + s0) * Kk;
    #pragma unroll
    for (int i = 0; i < 4; i++) {
        float4 v = acc[i];
        v.x += bv.x; v.y += bv.y; v.z += bv.z; v.w += bv.w;
        *(float4*)&outp[(size_t)(r0 + i) * Kk + c0] = v;
    }
}

// =============================================================================
// Kernel 2: attention for a 16-query slab of one (b,h).
//   scores (masked, scaled) -> smem, softmax in smem, write probs to d_out,
//   then P @ V fused.
// 256 threads, dynamic smem:
//   P  [16][2048] fp32, Qs [16][64], KV [128][68]
// grid: (S/16, B*H)
// =============================================================================
#define KV_STRIDE 68
#define SMEM_FLOATS (16*2048 + 16*64 + 128*KV_STRIDE)

__global__ __launch_bounds__(256) void attn_kernel(
    const int* __restrict__ mask, float* __restrict__ out_scores)
{
    extern __shared__ float sm[];
    float* P  = sm;                       // 16*2048
    float* Qs = sm + 16 * 2048;           // 16*64
    float* KV = Qs + 16 * 64;             // 128*68

    const int bh = blockIdx.y;
    const int b  = bh / Hh;
    const int s0 = blockIdx.x * 16;
    const int tid = threadIdx.x;

    const float* Qg = g_Q + ((size_t)bh * Ss + s0) * Kk;
    const float* Kg = g_K + (size_t)bh * Ss * Kk;
    const float* Vg = g_V + (size_t)bh * Ss * Kk;

    // load Q slab (16x64 = 1024 floats = 256 float4)
    ((float4*)Qs)[tid] = ((const float4*)Qg)[tid];

    // ---------------- scores: 16 x 2048 ----------------
    const int tc = tid % 32;        // key quad
    const int rc = tid / 32;        // 0..7 -> rows rc, rc+8
    const int* mrow0 = mask + ((size_t)b * Ss + s0 + rc)     * Ss;
    const int* mrow1 = mask + ((size_t)b * Ss + s0 + rc + 8) * Ss;

    for (int kt = 0; kt < Ss; kt += 128) {
        __syncthreads();   // protect KV reuse
        // load 128x64 K tile (rows padded to stride 68)
        for (int i = tid; i < 128 * 16; i += 256) {
            const int t = i / 16, kk = i % 16;
            ((float4*)(KV + t * KV_STRIDE))[kk] =
                ((const float4*)(Kg + (size_t)(kt + t) * Kk))[kk];
        }
        __syncthreads();

        float acc0[4] = {0.f, 0.f, 0.f, 0.f};
        float acc1[4] = {0.f, 0.f, 0.f, 0.f};
        #pragma unroll
        for (int k = 0; k < Kk; k += 4) {
            const float4 qa = *(const float4*)&Qs[rc * Kk + k];
            const float4 qb = *(const float4*)&Qs[(rc + 8) * Kk + k];
            #pragma unroll
            for (int i = 0; i < 4; i++) {
                const float4 kv = *(const float4*)&KV[(tc * 4 + i) * KV_STRIDE + k];
                acc0[i] += qa.x * kv.x + qa.y * kv.y + qa.z * kv.z + qa.w * kv.w;
                acc1[i] += qb.x * kv.x + qb.y * kv.y + qb.z * kv.z + qb.w * kv.w;
            }
        }
        #pragma unroll
        for (int i = 0; i < 4; i++) {
            const int t = kt + tc * 4 + i;
            P[rc * Ss + t]       = mrow0[t] ? acc0[i] * SCALE : -3.0e38f;
            P[(rc + 8) * Ss + t] = mrow1[t] ? acc1[i] * SCALE : -3.0e38f;
        }
    }
    __syncthreads();

    // ---------------- softmax (8 warps x 2 rows) + write probs --------------
    {
        const int warp = tid / 32, lane = tid % 32;
        #pragma unroll
        for (int rr = 0; rr < 2; rr++) {
            const int r = warp * 2 + rr;
            float* row = P + (size_t)r * Ss;
            float mx = -3.4e38f;
            for (int t = lane; t < Ss; t += 32) mx = fmaxf(mx, row[t]);
            #pragma unroll
            for (int o = 16; o > 0; o >>= 1) mx = fmaxf(mx, __shfl_xor_sync(0xffffffffu, mx, o));
            float sum = 0.f;
            for (int t = lane; t < Ss; t += 32) {
                const float e = __expf(row[t] - mx);
                row[t] = e;
                sum += e;
            }
            #pragma unroll
            for (int o = 16; o > 0; o >>= 1) sum += __shfl_xor_sync(0xffffffffu, sum, o);
            const float inv = 1.0f / sum;
            float* og = out_scores + ((size_t)bh * Ss + (s0 + r)) * Ss;
            for (int t = lane; t < Ss; t += 32) {
                const float p = row[t] * inv;
                row[t] = p;
                og[t]  = p;
            }
        }
    }
    __syncthreads();

    // ---------------- O = P @ V  (16 x 64) ----------------
    const int k0 = (tid % 16) * 4;
    const int r  = tid / 16;          // 0..15
    float4 o = make_float4(0.f, 0.f, 0.f, 0.f);
    for (int kt = 0; kt < Ss; kt += 128) {
        __syncthreads();
        for (int i = tid; i < 128 * 16; i += 256) {
            const int t = i / 16, kk = i % 16;
            ((float4*)(KV + t * KV_STRIDE))[kk] =
                ((const float4*)(Vg + (size_t)(kt + t) * Kk))[kk];
        }
        __syncthreads();
        #pragma unroll 4
        for (int t = 0; t < 128; t++) {
            const float p = P[(size_t)r * Ss + kt + t];
            const float4 v = *(const float4*)&KV[t * KV_STRIDE + k0];
            o.x += p * v.x; o.y += p * v.y; o.z += p * v.z; o.w += p * v.w;
        }
    }
    const int h = bh % Hh;
    *(float4*)&g_heads[((size_t)(b * Ss + s0 + r)) * (Hh * Kk) + h * Kk + k0] = o;
}

// =============================================================================
// Kernel 3: output projection.  heads [4096 x 1024] @ W_proj [1024 x 1024] + b_proj
// Same tiling as qkv. grid: (1024/64, 4096/64)
// =============================================================================
__global__ __launch_bounds__(256) void proj_kernel(
    const float* __restrict__ Wp, const float* __restrict__ bp,
    float* __restrict__ out)
{
    __shared__ float As[32][65];
    __shared__ float Bs[32][64];

    const int tid = threadIdx.x;
    const int n0 = blockIdx.x * 64;
    const int m0 = blockIdx.y * 64;
    const int HK = Hh * Kk;   // 1024

    const float* A = g_heads + (size_t)m0 * HK;

    const int c0 = (tid % 16) * 4;
    const int r0 = (tid / 16) * 4;

    float4 acc[4];
    #pragma unroll
    for (int i = 0; i < 4; i++) acc[i] = make_float4(0.f, 0.f, 0.f, 0.f);

    for (int d0 = 0; d0 < HK; d0 += 32) {
        {
            const int dd = tid % 32;
            const int rb = tid / 32;
            #pragma unroll
            for (int i = 0; i < 8; i++) {
                const int rr = i * 8 + rb;
                As[dd][rr] = A[(size_t)rr * HK + d0 + dd];
            }
        }
        {
            const int c  = tid % 64;
            const int db = tid / 64;
            #pragma unroll
            for (int i = 0; i < 8; i++) {
                const int dd = i * 4 + db;
                Bs[dd][c] = Wp[(size_t)(d0 + dd) * Dd + n0 + c];
            }
        }
        __syncthreads();
        #pragma unroll
        for (int dd = 0; dd < 32; dd++) {
            const float4 bv = *(const float4*)&Bs[dd][c0];
            float a0 = As[dd][r0 + 0], a1 = As[dd][r0 + 1];
            float a2 = As[dd][r0 + 2], a3 = As[dd][r0 + 3];
            acc[0].x += a0 * bv.x; acc[0].y += a0 * bv.y; acc[0].z += a0 * bv.z; acc[0].w += a0 * bv.w;
            acc[1].x += a1 * bv.x; acc[1].y += a1 * bv.y; acc[1].z += a1 * bv.z; acc[1].w += a1 * bv.w;
            acc[2].x += a2 * bv.x; acc[2].y += a2 * bv.y; acc[2].z += a2 * bv.z; acc[2].w += a2 * bv.w;
            acc[3].x += a3 * bv.x; acc[3].y += a3 * bv.y; acc[3].z += a3 * bv.z; acc[3].w += a3 * bv.w;
        }
        __syncthreads();
    }

    const float4 bv = *(const float4*)&bp[n0 + c0];
    #pragma unroll
    for (int i = 0; i < 4; i++) {
        float4 v = acc[i];
        v.x += bv.x; v.y += bv.y; v.z += bv.z; v.w += bv.w;
        *(float4*)&out[(size_t)(m0 + r0 + i) * Dd + n0 + c0] = v;
    }
}

// =============================================================================
extern "C" void kernel_launch(void* const* d_in, const int* in_sizes, int n_in,
                              void* d_out, int out_size)
{
    const float* x      = (const float*)d_in[0];
    const float* W_Q    = (const float*)d_in[1];
    const float* b_Q    = (const float*)d_in[2];
    const float* W_K    = (const float*)d_in[3];
    const float* b_K    = (const float*)d_in[4];
    const float* W_V    = (const float*)d_in[5];
    const float* b_V    = (const float*)d_in[6];
    const float* W_proj = (const float*)d_in[7];
    const float* b_proj = (const float*)d_in[8];
    const int*   amask  = (const int*)d_in[9];

    float* out        = (float*)d_out;                       // [B,S,D]
    float* out_scores = out + (size_t)Bb * Ss * Dd;          // [B,H,S,S]

    // QKV projections
    {
        dim3 grid(Ss / 64, BH, 3);
        qkv_kernel<<<grid, 256>>>(x, W_Q, b_Q, W_K, b_K, W_V, b_V);
    }

    // attention
    {
        const int smem = SMEM_FLOATS * (int)sizeof(float);   // ~170 KB
        cudaFuncSetAttribute(attn_kernel, cudaFuncAttributeMaxDynamicSharedMemorySize, smem);
        dim3 grid(Ss / 16, BH);
        attn_kernel<<<grid, 256, smem>>>(amask, out_scores);
    }

    // output projection
    {
        dim3 grid(Dd / 64, (Bb * Ss) / 64);
        proj_kernel<<<grid, 256>>>(W_proj, b_proj, out);
    }
}

// round 4
// speedup vs baseline: 2.4276x; 2.4241x over previous
#include <cuda_runtime.h>
#include <cuda_bf16.h>
#include <cstdint>

// Problem constants
#define Bb 2
#define Ss 2048
#define Dd 1024
#define Hh 16
#define Kk 64
#define BH (Bb*Hh)          // 32
#define SCALE 0.125f        // 1/sqrt(64)
#define NEGF  (-3.402823466e38f)

// ---------------- scratch (static device globals; no allocation) -------------
__device__ float g_Q[(size_t)BH * Ss * Kk];          // [bh, s, k] 16 MB
__device__ float g_K[(size_t)BH * Ss * Kk];          // 16 MB
__device__ float g_V[(size_t)BH * Ss * Kk];          // 16 MB
__device__ float g_heads[(size_t)Bb * Ss * Hh * Kk]; // [b, s, h*K] 16 MB

// 64-FMA micro-kernel helper
#define MICRO_FMA(acc, a0, a1, b0, b1)                                   \
    {                                                                    \
        float _a[8] = {a0.x, a0.y, a0.z, a0.w, a1.x, a1.y, a1.z, a1.w};  \
        float _b[8] = {b0.x, b0.y, b0.z, b0.w, b1.x, b1.y, b1.z, b1.w};  \
        _Pragma("unroll")                                                \
        for (int _i = 0; _i < 8; _i++) {                                 \
            _Pragma("unroll")                                            \
            for (int _j = 0; _j < 8; _j++)                               \
                acc[_i][_j] += _a[_i] * _b[_j];                          \
        }                                                                \
    }

// =============================================================================
// Kernel 1: QKV projection.  X[b] (S x D) @ W[h] (D x 64) + bias
// 128 threads, BM=128, BN=64, BK=32, micro 8x8.
// grid: (S/128, B*H, 3)
// =============================================================================
__global__ __launch_bounds__(128) void qkv_kernel(
    const float* __restrict__ x,
    const float* __restrict__ W_Q, const float* __restrict__ b_Q,
    const float* __restrict__ W_K, const float* __restrict__ b_K,
    const float* __restrict__ W_V, const float* __restrict__ b_V)
{
    const int stile = blockIdx.x;
    const int bh    = blockIdx.y;
    const int which = blockIdx.z;
    const int b = bh / Hh, h = bh % Hh;

    const float* W    = (which == 0) ? W_Q : (which == 1) ? W_K : W_V;
    const float* bias = (which == 0) ? b_Q : (which == 1) ? b_K : b_V;
    float*       out  = (which == 0) ? g_Q : (which == 1) ? g_K : g_V;

    __shared__ float At[32][132];   // A transposed: At[d][row]
    __shared__ float Bs[32][68];    // Bs[d][col]

    const int tid = threadIdx.x;
    const int s0 = stile * 128;
    const float* Ax = x + ((size_t)b * Ss + s0) * Dd;
    const float* Wh = W + (size_t)h * Dd * Kk;

    const int r0 = (tid >> 3) << 3;   // 0..120
    const int c0 = (tid & 7) << 3;    // 0..56

    float acc[8][8];
    #pragma unroll
    for (int i = 0; i < 8; i++)
        #pragma unroll
        for (int j = 0; j < 8; j++) acc[i][j] = 0.f;

    for (int d0 = 0; d0 < Dd; d0 += 32) {
        // load + transpose A tile (128 x 32)
        #pragma unroll
        for (int it = 0; it < 8; it++) {
            const int idx = it * 128 + tid;
            const int row = idx >> 3;
            const int k4  = (idx & 7) << 2;
            const float4 v = *(const float4*)&Ax[(size_t)row * Dd + d0 + k4];
            At[k4 + 0][row] = v.x; At[k4 + 1][row] = v.y;
            At[k4 + 2][row] = v.z; At[k4 + 3][row] = v.w;
        }
        // load B tile (32 x 64)
        #pragma unroll
        for (int it = 0; it < 4; it++) {
            const int idx = it * 128 + tid;
            const int dd = idx >> 4;
            const int c4 = (idx & 15) << 2;
            *(float4*)&Bs[dd][c4] = *(const float4*)&Wh[(size_t)(d0 + dd) * Kk + c4];
        }
        __syncthreads();
        #pragma unroll
        for (int dd = 0; dd < 32; dd++) {
            const float4 a0 = *(const float4*)&At[dd][r0];
            const float4 a1 = *(const float4*)&At[dd][r0 + 4];
            const float4 b0 = *(const float4*)&Bs[dd][c0];
            const float4 b1 = *(const float4*)&Bs[dd][c0 + 4];
            MICRO_FMA(acc, a0, a1, b0, b1);
        }
        __syncthreads();
    }

    float bv[8];
    #pragma unroll
    for (int j = 0; j < 8; j++) bv[j] = bias[h * Kk + c0 + j];

    float* outp = out + ((size_t)bh * Ss + s0) * Kk;
    #pragma unroll
    for (int i = 0; i < 8; i++) {
        float4 o0, o1;
        o0.x = acc[i][0] + bv[0]; o0.y = acc[i][1] + bv[1];
        o0.z = acc[i][2] + bv[2]; o0.w = acc[i][3] + bv[3];
        o1.x = acc[i][4] + bv[4]; o1.y = acc[i][5] + bv[5];
        o1.z = acc[i][6] + bv[6]; o1.w = acc[i][7] + bv[7];
        *(float4*)&outp[(size_t)(r0 + i) * Kk + c0]     = o0;
        *(float4*)&outp[(size_t)(r0 + i) * Kk + c0 + 4] = o1;
    }
}

// =============================================================================
// Kernel 2: scores = mask(Q @ K^T * scale) -> out_scores.
// 256 threads, BM=BN=128, reduction K=64 fully in smem (transposed), micro 8x8.
// grid: (H, 256 tiles, B)  -- heads adjacent so mask tiles hit L2.
// =============================================================================
__global__ __launch_bounds__(256) void scores_kernel(
    const int* __restrict__ mask, float* __restrict__ out_scores)
{
    extern __shared__ float sm[];
    float (*Qt)[132] = (float(*)[132])sm;              // Qt[k][row]
    float (*Kt)[132] = (float(*)[132])(sm + 64 * 132); // Kt[k][col]

    const int h  = blockIdx.x;
    const int b  = blockIdx.z;
    const int bh = b * Hh + h;
    const int st = blockIdx.y & 15;
    const int tt = blockIdx.y >> 4;
    const int s0 = st * 128;
    const int t0 = tt * 128;
    const int tid = threadIdx.x;

    const float* Qg = g_Q + ((size_t)bh * Ss + s0) * Kk;
    const float* Kg = g_K + ((size_t)bh * Ss + t0) * Kk;

    // load + transpose Q and K tiles (each 128 x 64)
    #pragma unroll
    for (int it = 0; it < 8; it++) {
        const int idx = it * 256 + tid;
        const int row = idx >> 4;
        const int k4  = (idx & 15) << 2;
        const float4 q = *(const float4*)&Qg[(size_t)row * Kk + k4];
        Qt[k4 + 0][row] = q.x; Qt[k4 + 1][row] = q.y;
        Qt[k4 + 2][row] = q.z; Qt[k4 + 3][row] = q.w;
        const float4 k = *(const float4*)&Kg[(size_t)row * Kk + k4];
        Kt[k4 + 0][row] = k.x; Kt[k4 + 1][row] = k.y;
        Kt[k4 + 2][row] = k.z; Kt[k4 + 3][row] = k.w;
    }
    __syncthreads();

    const int r0 = (tid >> 4) << 3;   // query rows
    const int c0 = (tid & 15) << 3;   // key cols

    float acc[8][8];
    #pragma unroll
    for (int i = 0; i < 8; i++)
        #pragma unroll
        for (int j = 0; j < 8; j++) acc[i][j] = 0.f;

    #pragma unroll 8
    for (int k = 0; k < Kk; k++) {
        const float4 a0 = *(const float4*)&Qt[k][r0];
        const float4 a1 = *(const float4*)&Qt[k][r0 + 4];
        const float4 b0 = *(const float4*)&Kt[k][c0];
        const float4 b1 = *(const float4*)&Kt[k][c0 + 4];
        MICRO_FMA(acc, a0, a1, b0, b1);
    }

    // epilogue: mask + scale + store
    #pragma unroll
    for (int i = 0; i < 8; i++) {
        const int s = s0 + r0 + i;
        const int* mrow = mask + ((size_t)b * Ss + s) * Ss + t0;
        const int4 m0 = *(const int4*)&mrow[c0];
        const int4 m1 = *(const int4*)&mrow[c0 + 4];
        float4 o0, o1;
        o0.x = m0.x ? acc[i][0] * SCALE : NEGF;
        o0.y = m0.y ? acc[i][1] * SCALE : NEGF;
        o0.z = m0.z ? acc[i][2] * SCALE : NEGF;
        o0.w = m0.w ? acc[i][3] * SCALE : NEGF;
        o1.x = m1.x ? acc[i][4] * SCALE : NEGF;
        o1.y = m1.y ? acc[i][5] * SCALE : NEGF;
        o1.z = m1.z ? acc[i][6] * SCALE : NEGF;
        o1.w = m1.w ? acc[i][7] * SCALE : NEGF;
        float* orow = out_scores + ((size_t)bh * Ss + s) * Ss + t0;
        *(float4*)&orow[c0]     = o0;
        *(float4*)&orow[c0 + 4] = o1;
    }
}

// =============================================================================
// Kernel 3: in-place row softmax over out_scores. 256 threads, 1 row per block.
// grid: (BH * S)
// =============================================================================
__global__ __launch_bounds__(256) void softmax_kernel(float* __restrict__ scores)
{
    __shared__ float red[8];
    __shared__ float bcast;

    float4* row = (float4*)(scores + (size_t)blockIdx.x * Ss);
    const int tid = threadIdx.x;
    const int lane = tid & 31, warp = tid >> 5;

    float4 v0 = row[tid];
    float4 v1 = row[tid + 256];

    // max
    float mx = fmaxf(fmaxf(fmaxf(v0.x, v0.y), fmaxf(v0.z, v0.w)),
                     fmaxf(fmaxf(v1.x, v1.y), fmaxf(v1.z, v1.w)));
    #pragma unroll
    for (int o = 16; o > 0; o >>= 1) mx = fmaxf(mx, __shfl_xor_sync(0xffffffffu, mx, o));
    if (lane == 0) red[warp] = mx;
    __syncthreads();
    if (tid == 0) {
        float m = red[0];
        #pragma unroll
        for (int i = 1; i < 8; i++) m = fmaxf(m, red[i]);
        bcast = m;
    }
    __syncthreads();
    mx = bcast;

    // exp + sum
    v0.x = __expf(v0.x - mx); v0.y = __expf(v0.y - mx);
    v0.z = __expf(v0.z - mx); v0.w = __expf(v0.w - mx);
    v1.x = __expf(v1.x - mx); v1.y = __expf(v1.y - mx);
    v1.z = __expf(v1.z - mx); v1.w = __expf(v1.w - mx);
    float sum = v0.x + v0.y + v0.z + v0.w + v1.x + v1.y + v1.z + v1.w;
    #pragma unroll
    for (int o = 16; o > 0; o >>= 1) sum += __shfl_xor_sync(0xffffffffu, sum, o);
    __syncthreads();
    if (lane == 0) red[warp] = sum;
    __syncthreads();
    if (tid == 0) {
        float s = 0.f;
        #pragma unroll
        for (int i = 0; i < 8; i++) s += red[i];
        bcast = 1.0f / s;
    }
    __syncthreads();
    const float inv = bcast;

    v0.x *= inv; v0.y *= inv; v0.z *= inv; v0.w *= inv;
    v1.x *= inv; v1.y *= inv; v1.z *= inv; v1.w *= inv;
    row[tid]       = v0;
    row[tid + 256] = v1;
}

// =============================================================================
// Kernel 4: heads = P @ V per (b,h).  M=2048(s), N=64(k), red=2048(t).
// 128 threads, BM=128, BN=64, BK=32, micro 8x8.
// grid: (S/128, BH)
// =============================================================================
__global__ __launch_bounds__(128) void pv_kernel(
    const float* __restrict__ probs)
{
    __shared__ float Pt[32][132];   // Pt[t][row]
    __shared__ float Vs[32][68];    // Vs[t][col]

    const int bh = blockIdx.y;
    const int b = bh / Hh, h = bh % Hh;
    const int s0 = blockIdx.x * 128;
    const int tid = threadIdx.x;

    const float* Pg = probs + ((size_t)bh * Ss + s0) * Ss;
    const float* Vg = g_V + (size_t)bh * Ss * Kk;

    const int r0 = (tid >> 3) << 3;
    const int c0 = (tid & 7) << 3;

    float acc[8][8];
    #pragma unroll
    for (int i = 0; i < 8; i++)
        #pragma unroll
        for (int j = 0; j < 8; j++) acc[i][j] = 0.f;

    for (int t0 = 0; t0 < Ss; t0 += 32) {
        // load + transpose P tile (128 x 32)
        #pragma unroll
        for (int it = 0; it < 8; it++) {
            const int idx = it * 128 + tid;
            const int row = idx >> 3;
            const int q4  = (idx & 7) << 2;
            const float4 v = *(const float4*)&Pg[(size_t)row * Ss + t0 + q4];
            Pt[q4 + 0][row] = v.x; Pt[q4 + 1][row] = v.y;
            Pt[q4 + 2][row] = v.z; Pt[q4 + 3][row] = v.w;
        }
        // load V tile (32 x 64)
        #pragma unroll
        for (int it = 0; it < 4; it++) {
            const int idx = it * 128 + tid;
            const int tt = idx >> 4;
            const int c4 = (idx & 15) << 2;
            *(float4*)&Vs[tt][c4] = *(const float4*)&Vg[(size_t)(t0 + tt) * Kk + c4];
        }
        __syncthreads();
        #pragma unroll
        for (int tt = 0; tt < 32; tt++) {
            const float4 a0 = *(const float4*)&Pt[tt][r0];
            const float4 a1 = *(const float4*)&Pt[tt][r0 + 4];
            const float4 b0 = *(const float4*)&Vs[tt][c0];
            const float4 b1 = *(const float4*)&Vs[tt][c0 + 4];
            MICRO_FMA(acc, a0, a1, b0, b1);
        }
        __syncthreads();
    }

    #pragma unroll
    for (int i = 0; i < 8; i++) {
        float* orow = g_heads + ((size_t)(b * Ss + s0 + r0 + i)) * (Hh * Kk) + h * Kk;
        float4 o0, o1;
        o0.x = acc[i][0]; o0.y = acc[i][1]; o0.z = acc[i][2]; o0.w = acc[i][3];
        o1.x = acc[i][4]; o1.y = acc[i][5]; o1.z = acc[i][6]; o1.w = acc[i][7];
        *(float4*)&orow[c0]     = o0;
        *(float4*)&orow[c0 + 4] = o1;
    }
}

// =============================================================================
// Kernel 5: out = heads (4096 x 1024) @ W_proj (1024 x 1024) + b_proj.
// 128 threads, BM=128, BN=64, BK=32, micro 8x8.
// grid: (1024/64, 4096/128)
// =============================================================================
__global__ __launch_bounds__(128) void proj_kernel(
    const float* __restrict__ Wp, const float* __restrict__ bp,
    float* __restrict__ out)
{
    __shared__ float At[32][132];
    __shared__ float Bs[32][68];

    const int tid = threadIdx.x;
    const int n0 = blockIdx.x * 64;
    const int m0 = blockIdx.y * 128;
    const int HK = Hh * Kk;   // 1024

    const float* A = g_heads + (size_t)m0 * HK;

    const int r0 = (tid >> 3) << 3;
    const int c0 = (tid & 7) << 3;

    float acc[8][8];
    #pragma unroll
    for (int i = 0; i < 8; i++)
        #pragma unroll
        for (int j = 0; j < 8; j++) acc[i][j] = 0.f;

    for (int d0 = 0; d0 < HK; d0 += 32) {
        #pragma unroll
        for (int it = 0; it < 8; it++) {
            const int idx = it * 128 + tid;
            const int row = idx >> 3;
            const int k4  = (idx & 7) << 2;
            const float4 v = *(const float4*)&A[(size_t)row * HK + d0 + k4];
            At[k4 + 0][row] = v.x; At[k4 + 1][row] = v.y;
            At[k4 + 2][row] = v.z; At[k4 + 3][row] = v.w;
        }
        #pragma unroll
        for (int it = 0; it < 4; it++) {
            const int idx = it * 128 + tid;
            const int dd = idx >> 4;
            const int c4 = (idx & 15) << 2;
            *(float4*)&Bs[dd][c4] = *(const float4*)&Wp[(size_t)(d0 + dd) * Dd + n0 + c4];
        }
        __syncthreads();
        #pragma unroll
        for (int dd = 0; dd < 32; dd++) {
            const float4 a0 = *(const float4*)&At[dd][r0];
            const float4 a1 = *(const float4*)&At[dd][r0 + 4];
            const float4 b0 = *(const float4*)&Bs[dd][c0];
            const float4 b1 = *(const float4*)&Bs[dd][c0 + 4];
            MICRO_FMA(acc, a0, a1, b0, b1);
        }
        __syncthreads();
    }

    float bv[8];
    #pragma unroll
    for (int j = 0; j < 8; j++) bv[j] = bp[n0 + c0 + j];

    #pragma unroll
    for (int i = 0; i < 8; i++) {
        float4 o0, o1;
        o0.x = acc[i][0] + bv[0]; o0.y = acc[i][1] + bv[1];
        o0.z = acc[i][2] + bv[2]; o0.w = acc[i][3] + bv[3];
        o1.x = acc[i][4] + bv[4]; o1.y = acc[i][5] + bv[5];
        o1.z = acc[i][6] + bv[6]; o1.w = acc[i][7] + bv[7];
        *(float4*)&out[(size_t)(m0 + r0 + i) * Dd + n0 + c0]     = o0;
        *(float4*)&out[(size_t)(m0 + r0 + i) * Dd + n0 + c0 + 4] = o1;
    }
}

// =============================================================================
extern "C" void kernel_launch(void* const* d_in, const int* in_sizes, int n_in,
                              void* d_out, int out_size)
{
    const float* x      = (const float*)d_in[0];
    const float* W_Q    = (const float*)d_in[1];
    const float* b_Q    = (const float*)d_in[2];
    const float* W_K    = (const float*)d_in[3];
    const float* b_K    = (const float*)d_in[4];
    const float* W_V    = (const float*)d_in[5];
    const float* b_V    = (const float*)d_in[6];
    const float* W_proj = (const float*)d_in[7];
    const float* b_proj = (const float*)d_in[8];
    const int*   amask  = (const int*)d_in[9];

    float* out        = (float*)d_out;                       // [B,S,D]
    float* out_scores = out + (size_t)Bb * Ss * Dd;          // [B,H,S,S]

    // 1) QKV projections
    {
        dim3 grid(Ss / 128, BH, 3);
        qkv_kernel<<<grid, 128>>>(x, W_Q, b_Q, W_K, b_K, W_V, b_V);
    }

    // 2) masked, scaled scores -> out_scores
    {
        const int smem = 2 * 64 * 132 * (int)sizeof(float);   // 67.6 KB
        cudaFuncSetAttribute(scores_kernel, cudaFuncAttributeMaxDynamicSharedMemorySize, smem);
        dim3 grid(Hh, (Ss / 128) * (Ss / 128), Bb);
        scores_kernel<<<grid, 256, smem>>>(amask, out_scores);
    }

    // 3) in-place softmax
    {
        softmax_kernel<<<BH * Ss, 256>>>(out_scores);
    }

    // 4) P @ V -> g_heads
    {
        dim3 grid(Ss / 128, BH);
        pv_kernel<<<grid, 128>>>(out_scores);
    }

    // 5) output projection
    {
        dim3 grid(Dd / 64, (Bb * Ss) / 128);
        proj_kernel<<<grid, 128>>>(W_proj, b_proj, out);
    }
}